// round 4
// baseline (speedup 1.0000x reference)
#include <cuda_runtime.h>

// S=64, B=128, D=10000 fixed by the reference.
#define D_DIM   10000
#define D4      2500
#define J_FULL  78            // 78*32 = 2496 float4; tail = 4
#define S_DIM   64
#define B_DIM   128
#define THREADS 512
#define NWARPS  16
#define SMEM_BYTES (2 * D_DIM * sizeof(float))   // 80000 B

__device__ float    g_partial[B_DIM];
__device__ unsigned g_ticket;      // zero-init; reset by last CTA each launch

__global__ __launch_bounds__(THREADS, 1)
void pl_fused(const float* __restrict__ theta,
              const float* __restrict__ y,
              const float* __restrict__ noise,
              float* __restrict__ out)
{
    extern __shared__ float sm[];          // [0,10000): theta_b  [10000,20000): y_b
    float* __restrict__ sth = sm;
    float* __restrict__ syy = sm + D_DIM;
    __shared__ float fin[NWARPS];
    __shared__ int   is_last;

    const int b    = blockIdx.x;
    const int tid  = threadIdx.x;
    const int lane = tid & 31;
    const int warp = tid >> 5;

    // ---- stage theta_b, y_b into shared (only DRAM touch for them) ----
    {
        const float4* __restrict__ th4 = (const float4*)(theta + (size_t)b * D_DIM);
        const float4* __restrict__ yy4 = (const float4*)(y     + (size_t)b * D_DIM);
        float4* s_t = (float4*)sth;
        float4* s_y = (float4*)syy;
        for (int i = tid; i < D4; i += THREADS) {
            s_t[i] = __ldg(th4 + i);
            s_y[i] = __ldg(yy4 + i);
        }
    }
    __syncthreads();

    const float4* __restrict__ st4 = (const float4*)sth;
    const float4* __restrict__ sy4 = (const float4*)syy;

    // ---- per-warp Sigma(y^2) over full D (sample-invariant) ----
    float sy2 = 0.0f;
    for (int j = 0; j < J_FULL; j++) {
        float4 v = sy4[j * 32 + lane];
        sy2 = fmaf(v.x, v.x, sy2);
        sy2 = fmaf(v.y, v.y, sy2);
        sy2 = fmaf(v.z, v.z, sy2);
        sy2 = fmaf(v.w, v.w, sy2);
    }
    if (lane < 4) {
        float4 v = sy4[2496 + lane];
        sy2 = fmaf(v.x, v.x, sy2);
        sy2 = fmaf(v.y, v.y, sy2);
        sy2 = fmaf(v.z, v.z, sy2);
        sy2 = fmaf(v.w, v.w, sy2);
    }
    #pragma unroll
    for (int o = 16; o; o >>= 1) sy2 += __shfl_xor_sync(0xffffffffu, sy2, o);

    // ---- 4 rounds x 16 warps = 64 samples; no block barriers ----
    float acc = 0.0f;
    #pragma unroll 1
    for (int r = 0; r < 4; r++) {
        const int s = r * NWARPS + warp;
        const float4* __restrict__ nz =
            (const float4*)(noise + ((size_t)s * B_DIM + b) * D_DIM);

        float sq = 0.0f, sq2 = 0.0f, sqy = 0.0f;
        #pragma unroll 6
        for (int j = 0; j < J_FULL; j++) {
            const int idx = j * 32 + lane;
            float4 n = __ldcs(nz + idx);
            float4 t = st4[idx];
            float4 yv = sy4[idx];
            float qx = __expf(t.x + n.x);
            float qy = __expf(t.y + n.y);
            float qz = __expf(t.z + n.z);
            float qw = __expf(t.w + n.w);
            sq  += (qx + qy) + (qz + qw);
            sq2 = fmaf(qx, qx, sq2);  sq2 = fmaf(qy, qy, sq2);
            sq2 = fmaf(qz, qz, sq2);  sq2 = fmaf(qw, qw, sq2);
            sqy = fmaf(qx, yv.x, sqy); sqy = fmaf(qy, yv.y, sqy);
            sqy = fmaf(qz, yv.z, sqy); sqy = fmaf(qw, yv.w, sqy);
        }
        if (lane < 4) {   // tail: float4 indices 2496..2499
            const int idx = 2496 + lane;
            float4 n = __ldcs(nz + idx);
            float4 t = st4[idx];
            float4 yv = sy4[idx];
            float qx = __expf(t.x + n.x);
            float qy = __expf(t.y + n.y);
            float qz = __expf(t.z + n.z);
            float qw = __expf(t.w + n.w);
            sq  += (qx + qy) + (qz + qw);
            sq2 = fmaf(qx, qx, sq2);  sq2 = fmaf(qy, qy, sq2);
            sq2 = fmaf(qz, qz, sq2);  sq2 = fmaf(qw, qw, sq2);
            sqy = fmaf(qx, yv.x, sqy); sqy = fmaf(qy, yv.y, sqy);
            sqy = fmaf(qz, yv.z, sqy); sqy = fmaf(qw, yv.w, sqy);
        }

        // warp-local reductions (the only softmax "sync" needed)
        #pragma unroll
        for (int o = 16; o; o >>= 1) {
            sq  += __shfl_xor_sync(0xffffffffu, sq,  o);
            sq2 += __shfl_xor_sync(0xffffffffu, sq2, o);
            sqy += __shfl_xor_sync(0xffffffffu, sqy, o);
        }
        const float inv = __frcp_rn(sq);
        // loss_s = inv^2*Sq2 - 2*inv*Sqy + Sy2
        acc += fmaf(inv * inv, sq2, fmaf(-2.0f * inv, sqy, sy2));
    }

    // ---- block combine (single barrier) + fused grid reduction ----
    if (lane == 0) fin[warp] = acc;
    __syncthreads();
    if (tid == 0) {
        float tot = fin[0];
        #pragma unroll
        for (int w = 1; w < NWARPS; w++) tot += fin[w];
        g_partial[b] = tot;
        __threadfence();
        unsigned t = atomicAdd(&g_ticket, 1u);
        is_last = (t == B_DIM - 1) ? 1 : 0;
    }
    __syncthreads();

    if (is_last) {
        if (tid < B_DIM) {
            float v = __ldcg(&g_partial[tid]);
            #pragma unroll
            for (int o = 16; o; o >>= 1) v += __shfl_xor_sync(0xffffffffu, v, o);
            if (lane == 0) fin[warp] = v;      // warps 0..3
        }
        __syncthreads();
        if (tid == 0) {
            float tot = fin[0] + fin[1] + fin[2] + fin[3];
            out[0] = tot * (1.0f / ((float)S_DIM * (float)B_DIM * (float)D_DIM));
            g_ticket = 0u;                      // reset for next graph replay
        }
    }
}

extern "C" void kernel_launch(void* const* d_in, const int* in_sizes, int n_in,
                              void* d_out, int out_size)
{
    const float* theta = (const float*)d_in[0];  // [B, D]
    const float* y     = (const float*)d_in[1];  // [B, D]
    const float* noise = (const float*)d_in[2];  // [S, B, D]
    float* out = (float*)d_out;

    cudaFuncSetAttribute(pl_fused,
                         cudaFuncAttributeMaxDynamicSharedMemorySize,
                         SMEM_BYTES);
    pl_fused<<<B_DIM, THREADS, SMEM_BYTES>>>(theta, y, noise, out);
}

// round 5
// speedup vs baseline: 1.0950x; 1.0950x over previous
#include <cuda_runtime.h>

// S=64, B=128, D=10000 fixed by the reference.
#define D_DIM   10000
#define D4      2500
#define J_FULL  78            // 78*32 = 2496 float4; tail = 4
#define S_DIM   64
#define B_DIM   128
#define THREADS 1024
#define NWARPS  32
#define SMEM_BYTES (2 * D_DIM * sizeof(float))   // 80000 B

__device__ float    g_partial[B_DIM];
__device__ unsigned g_ticket;      // zero-init; reset by last CTA each launch

__global__ __launch_bounds__(THREADS, 1)
void pl_fused(const float* __restrict__ theta,
              const float* __restrict__ y,
              const float* __restrict__ noise,
              float* __restrict__ out)
{
    extern __shared__ float sm[];          // [0,10000): theta_b  [10000,20000): y_b
    float* __restrict__ sth = sm;
    float* __restrict__ syy = sm + D_DIM;
    __shared__ float fin[NWARPS];
    __shared__ int   is_last;

    const int b    = blockIdx.x;
    const int tid  = threadIdx.x;
    const int lane = tid & 31;
    const int warp = tid >> 5;

    // ---- stage theta_b, y_b into shared (only DRAM touch for them) ----
    {
        const float4* __restrict__ th4 = (const float4*)(theta + (size_t)b * D_DIM);
        const float4* __restrict__ yy4 = (const float4*)(y     + (size_t)b * D_DIM);
        float4* s_t = (float4*)sth;
        float4* s_y = (float4*)syy;
        for (int i = tid; i < D4; i += THREADS) {
            s_t[i] = __ldg(th4 + i);
            s_y[i] = __ldg(yy4 + i);
        }
    }
    __syncthreads();

    const float4* __restrict__ st4 = (const float4*)sth;
    const float4* __restrict__ sy4 = (const float4*)syy;

    // ---- per-warp Sigma(y^2) over full D (sample-invariant) ----
    float sy2 = 0.0f;
    for (int j = 0; j < J_FULL; j++) {
        float4 v = sy4[j * 32 + lane];
        sy2 = fmaf(v.x, v.x, sy2);
        sy2 = fmaf(v.y, v.y, sy2);
        sy2 = fmaf(v.z, v.z, sy2);
        sy2 = fmaf(v.w, v.w, sy2);
    }
    if (lane < 4) {
        float4 v = sy4[2496 + lane];
        sy2 = fmaf(v.x, v.x, sy2);
        sy2 = fmaf(v.y, v.y, sy2);
        sy2 = fmaf(v.z, v.z, sy2);
        sy2 = fmaf(v.w, v.w, sy2);
    }
    #pragma unroll
    for (int o = 16; o; o >>= 1) sy2 += __shfl_xor_sync(0xffffffffu, sy2, o);

    // ---- 2 rounds x 32 warps = 64 samples; no block barriers ----
    float acc = 0.0f;
    #pragma unroll 1
    for (int r = 0; r < 2; r++) {
        const int s = r * NWARPS + warp;
        const float4* __restrict__ nz =
            (const float4*)(noise + ((size_t)s * B_DIM + b) * D_DIM);

        float sq = 0.0f, sq2 = 0.0f, sqy = 0.0f;
        #pragma unroll 6
        for (int j = 0; j < J_FULL; j++) {
            const int idx = j * 32 + lane;
            float4 n = __ldcs(nz + idx);
            float4 t = st4[idx];
            float4 yv = sy4[idx];
            float qx = __expf(t.x + n.x);
            float qy = __expf(t.y + n.y);
            float qz = __expf(t.z + n.z);
            float qw = __expf(t.w + n.w);
            sq  += (qx + qy) + (qz + qw);
            sq2 = fmaf(qx, qx, sq2);  sq2 = fmaf(qy, qy, sq2);
            sq2 = fmaf(qz, qz, sq2);  sq2 = fmaf(qw, qw, sq2);
            sqy = fmaf(qx, yv.x, sqy); sqy = fmaf(qy, yv.y, sqy);
            sqy = fmaf(qz, yv.z, sqy); sqy = fmaf(qw, yv.w, sqy);
        }
        if (lane < 4) {   // tail: float4 indices 2496..2499
            const int idx = 2496 + lane;
            float4 n = __ldcs(nz + idx);
            float4 t = st4[idx];
            float4 yv = sy4[idx];
            float qx = __expf(t.x + n.x);
            float qy = __expf(t.y + n.y);
            float qz = __expf(t.z + n.z);
            float qw = __expf(t.w + n.w);
            sq  += (qx + qy) + (qz + qw);
            sq2 = fmaf(qx, qx, sq2);  sq2 = fmaf(qy, qy, sq2);
            sq2 = fmaf(qz, qz, sq2);  sq2 = fmaf(qw, qw, sq2);
            sqy = fmaf(qx, yv.x, sqy); sqy = fmaf(qy, yv.y, sqy);
            sqy = fmaf(qz, yv.z, sqy); sqy = fmaf(qw, yv.w, sqy);
        }

        // warp-local reductions (the only softmax "sync" needed)
        #pragma unroll
        for (int o = 16; o; o >>= 1) {
            sq  += __shfl_xor_sync(0xffffffffu, sq,  o);
            sq2 += __shfl_xor_sync(0xffffffffu, sq2, o);
            sqy += __shfl_xor_sync(0xffffffffu, sqy, o);
        }
        const float inv = __frcp_rn(sq);
        // loss_s = inv^2*Sq2 - 2*inv*Sqy + Sy2
        acc += fmaf(inv * inv, sq2, fmaf(-2.0f * inv, sqy, sy2));
    }

    // ---- block combine (single barrier) + fused grid reduction ----
    if (lane == 0) fin[warp] = acc;
    __syncthreads();
    if (tid == 0) {
        float tot = fin[0];
        #pragma unroll
        for (int w = 1; w < NWARPS; w++) tot += fin[w];
        g_partial[b] = tot;
        __threadfence();
        unsigned t = atomicAdd(&g_ticket, 1u);
        is_last = (t == B_DIM - 1) ? 1 : 0;
    }
    __syncthreads();

    if (is_last) {
        float v = 0.0f;
        if (tid < B_DIM) {
            v = __ldcg(&g_partial[tid]);
            #pragma unroll
            for (int o = 16; o; o >>= 1) v += __shfl_xor_sync(0xffffffffu, v, o);
            if (lane == 0) fin[warp] = v;      // warps 0..3
        }
        __syncthreads();
        if (tid == 0) {
            float tot = fin[0] + fin[1] + fin[2] + fin[3];
            out[0] = tot * (1.0f / ((float)S_DIM * (float)B_DIM * (float)D_DIM));
            g_ticket = 0u;                      // reset for next graph replay
        }
    }
}

extern "C" void kernel_launch(void* const* d_in, const int* in_sizes, int n_in,
                              void* d_out, int out_size)
{
    const float* theta = (const float*)d_in[0];  // [B, D]
    const float* y     = (const float*)d_in[1];  // [B, D]
    const float* noise = (const float*)d_in[2];  // [S, B, D]
    float* out = (float*)d_out;

    cudaFuncSetAttribute(pl_fused,
                         cudaFuncAttributeMaxDynamicSharedMemorySize,
                         SMEM_BYTES);
    pl_fused<<<B_DIM, THREADS, SMEM_BYTES>>>(theta, y, noise, out);
}